// round 2
// baseline (speedup 1.0000x reference)
#include <cuda_runtime.h>

#define N 256
#define PAD 257
#define SR 192          // rows resident in shared memory
#define RR 64           // rows resident in registers (2 per lane)
#define ITERS 20
#define THREADS 1024

__global__ __launch_bounds__(THREADS, 1)
void sinkhorn_kernel(const float* __restrict__ x, float* __restrict__ out) {
    extern __shared__ float sm[];
    float* Ks      = sm;                 // SR*PAD floats
    float* A       = Ks + SR * PAD;      // 256
    float* B       = A + N;              // 256
    float* rowpart = B + N;              // 32*RR = 2048 (main loop)
    float* stage   = rowpart;            // 16*PAD = 4112 (setup/epilogue only, overlaps rowpart)

    const int t = threadIdx.x;
    const int l = t & 31;
    const int w = t >> 5;
    const size_t base = (size_t)blockIdx.x * (N * N);
    const float* xm = x + base;
    float* om = out + base;

    // ---- setup: K = exp(x) for shared-memory rows (coalesced, padded store) ----
    for (int idx = t; idx < SR * N; idx += THREADS) {
        int i = idx >> 8, j = idx & 255;
        Ks[i * PAD + j] = __expf(xm[idx]);
    }
    if (t < N) A[t] = 1.0f;

    // ---- setup: register rows SR..255 via staging (coalesced gmem, conflict-light LDS) ----
    // warp w owns columns {w + 32c}; lane l owns rows SR+2l and SR+2l+1.
    float Kr[2][8];
    #pragma unroll
    for (int q = 0; q < 4; q++) {
        __syncthreads();
        for (int idx = t; idx < 16 * N; idx += THREADS) {
            int i = idx >> 8, j = idx & 255;
            stage[i * PAD + j] = __expf(xm[(SR + 16 * q + i) * N + j]);
        }
        __syncthreads();
        #pragma unroll
        for (int p = 0; p < 2; p++) {
            int r2 = 2 * l + p;
            if (r2 >= 16 * q && r2 < 16 * q + 16) {
                #pragma unroll
                for (int c = 0; c < 8; c++)
                    Kr[p][c] = stage[(r2 - 16 * q) * PAD + w + 32 * c];
            }
        }
    }
    __syncthreads();

    // ---- main Sinkhorn loop (linear domain) ----
    for (int it = 0; it < ITERS; it++) {
        // ===== column pass: B_j = 1 / sum_i K_ij * A_i =====
        float Av[6], Ar[2];
        #pragma unroll
        for (int r = 0; r < 6; r++) Av[r] = A[l + 32 * r];
        #pragma unroll
        for (int p = 0; p < 2; p++) Ar[p] = A[SR + 2 * l + p];

        #pragma unroll
        for (int c = 0; c < 8; c++) {
            int j = w + 32 * c;
            float acc = 0.0f;
            #pragma unroll
            for (int r = 0; r < 6; r++)          // smem rows: bank = (l+j)%32, conflict-free
                acc = fmaf(Ks[(l + 32 * r) * PAD + j], Av[r], acc);
            #pragma unroll
            for (int p = 0; p < 2; p++)          // register rows
                acc = fmaf(Kr[p][c], Ar[p], acc);
            #pragma unroll
            for (int s = 16; s > 0; s >>= 1)
                acc += __shfl_xor_sync(0xffffffffu, acc, s);
            if (l == c) B[j] = 1.0f / acc;
        }
        __syncthreads();

        // ===== row pass: A_i = 1 / sum_j K_ij * B_j =====
        float Bv[8];
        #pragma unroll
        for (int b = 0; b < 8; b++) Bv[b] = B[l + 32 * b];
        #pragma unroll
        for (int r = 0; r < 6; r++) {
            int i = w + 32 * r;
            float acc = 0.0f;
            #pragma unroll
            for (int b = 0; b < 8; b++)          // bank = (i+l)%32, conflict-free
                acc = fmaf(Ks[i * PAD + l + 32 * b], Bv[b], acc);
            #pragma unroll
            for (int s = 16; s > 0; s >>= 1)
                acc += __shfl_xor_sync(0xffffffffu, acc, s);
            if (l == r) A[i] = 1.0f / acc;
        }
        // register rows: per-warp partial row sums, combined across warps in smem
        float Bw[8];
        #pragma unroll
        for (int c = 0; c < 8; c++) Bw[c] = B[w + 32 * c];   // broadcast
        #pragma unroll
        for (int p = 0; p < 2; p++) {
            float acc = 0.0f;
            #pragma unroll
            for (int c = 0; c < 8; c++)
                acc = fmaf(Kr[p][c], Bw[c], acc);
            rowpart[w * RR + 2 * l + p] = acc;
        }
        __syncthreads();
        if (t < RR) {
            float acc = 0.0f;
            #pragma unroll
            for (int ww = 0; ww < 32; ww++)
                acc += rowpart[ww * RR + t];
            A[SR + t] = 1.0f / acc;
        }
        __syncthreads();
    }

    // ---- epilogue: out = K * A_i * B_j ----
    for (int idx = t; idx < SR * N; idx += THREADS) {
        int i = idx >> 8, j = idx & 255;
        om[idx] = Ks[i * PAD + j] * A[i] * B[j];
    }
    #pragma unroll
    for (int q = 0; q < 4; q++) {
        __syncthreads();
        #pragma unroll
        for (int p = 0; p < 2; p++) {
            int r2 = 2 * l + p;
            if (r2 >= 16 * q && r2 < 16 * q + 16) {
                float a = A[SR + r2];
                #pragma unroll
                for (int c = 0; c < 8; c++)
                    stage[(r2 - 16 * q) * PAD + w + 32 * c] = Kr[p][c] * a * B[w + 32 * c];
            }
        }
        __syncthreads();
        for (int idx = t; idx < 16 * N; idx += THREADS) {
            int i = idx >> 8, j = idx & 255;
            om[(SR + 16 * q + i) * N + j] = stage[i * PAD + j];
        }
    }
}

extern "C" void kernel_launch(void* const* d_in, const int* in_sizes, int n_in,
                              void* d_out, int out_size) {
    const float* x = (const float*)d_in[0];
    float* out = (float*)d_out;
    int n_mat = in_sizes[0] / (N * N);   // 512
    size_t smem = (size_t)(SR * PAD + 2 * N + 16 * PAD) * sizeof(float);  // 215872 B
    cudaFuncSetAttribute(sinkhorn_kernel,
                         cudaFuncAttributeMaxDynamicSharedMemorySize, (int)smem);
    sinkhorn_kernel<<<n_mat, THREADS, smem>>>(x, out);
}

// round 3
// speedup vs baseline: 1.8648x; 1.8648x over previous
#include <cuda_runtime.h>
#include <cuda_fp16.h>

#define NN     256
#define HSTR   264          // halves per matrix row in smem (= 33 uint4, 1 uint4 pad)
#define U4STR  33           // row stride in uint4
#define ITERS  20
#define THREADS 1024

// smem layout:
//   Kh  : 256 * 264 halves               = 135168 B
//   red : 8448 floats (shared col/row)   =  33792 B
//   A   : 256 floats
//   Bt  : 256 floats  (B permuted: Bt[e*32+u] = B[8u+e])
#define SM_BYTES (NN*HSTR*2 + (8448 + 2*NN) * 4)

__global__ __launch_bounds__(THREADS, 1)
void sinkhorn_kernel(const float* __restrict__ x, float* __restrict__ out) {
    extern __shared__ char smraw[];
    __half* Kh  = (__half*)smraw;
    uint4*  Kh4 = (uint4*)smraw;
    float*  red = (float*)(smraw + NN * HSTR * 2);
    float*  A   = red + 8448;
    float*  Bt  = A + NN;

    const int t = threadIdx.x;
    const int u = t & 31;        // uint4-column: halves 8u..8u+7
    const int s = t >> 5;        // row-slice: rows 8s..8s+7 (s == warp id)
    const size_t base = (size_t)blockIdx.x * (NN * NN);
    const float* xm = x + base;
    float* om = out + base;

    // ---------------- setup: Kh = fp16(exp(x)) ----------------
    #pragma unroll 4
    for (int k = 0; k < 16; k++) {
        int idx = (k * THREADS + t) * 4;
        float4 v = *(const float4*)(xm + idx);
        __half2 h0 = __floats2half2_rn(__expf(v.x), __expf(v.y));
        __half2 h1 = __floats2half2_rn(__expf(v.z), __expf(v.w));
        int i = idx >> 8, j = idx & 255;
        *(__half2*)(Kh + i * HSTR + j)     = h0;
        *(__half2*)(Kh + i * HSTR + j + 2) = h1;
    }
    if (t < NN) A[t] = 1.0f;
    __syncthreads();

    // ---------------- main loop (linear-domain Sinkhorn) ----------------
    for (int it = 0; it < ITERS; it++) {
        // ===== column pass: B_j = 1 / sum_i K[i][j] * A[i] =====
        float4 a0 = *(const float4*)(A + 8 * s);      // warp-uniform broadcasts
        float4 a1 = *(const float4*)(A + 8 * s + 4);
        float Areg[8] = {a0.x, a0.y, a0.z, a0.w, a1.x, a1.y, a1.z, a1.w};
        float acc[8] = {0,0,0,0,0,0,0,0};
        #pragma unroll
        for (int r = 0; r < 8; r++) {
            uint4 kv = Kh4[(8 * s + r) * U4STR + u];
            float ar = Areg[r];
            float2 f;
            f = __half22float2(*(__half2*)&kv.x);
            acc[0] = fmaf(f.x, ar, acc[0]); acc[1] = fmaf(f.y, ar, acc[1]);
            f = __half22float2(*(__half2*)&kv.y);
            acc[2] = fmaf(f.x, ar, acc[2]); acc[3] = fmaf(f.y, ar, acc[3]);
            f = __half22float2(*(__half2*)&kv.z);
            acc[4] = fmaf(f.x, ar, acc[4]); acc[5] = fmaf(f.y, ar, acc[5]);
            f = __half22float2(*(__half2*)&kv.w);
            acc[6] = fmaf(f.x, ar, acc[6]); acc[7] = fmaf(f.y, ar, acc[7]);
        }
        // stage partials: red[e][u][s], banks = (u+s)%32 -> conflict-free
        #pragma unroll
        for (int e = 0; e < 8; e++) red[e * 1056 + u * 33 + s] = acc[e];
        __syncthreads();
        if (t < NN) {   // column j = 8*u2 + e2 ; reduce over 32 slices
            int u2 = t & 31, e2 = t >> 5;
            const float* p = red + e2 * 1056 + u2 * 33;
            float c0 = 0, c1 = 0, c2 = 0, c3 = 0;
            #pragma unroll
            for (int k = 0; k < 32; k += 4) {
                c0 += p[k]; c1 += p[k + 1]; c2 += p[k + 2]; c3 += p[k + 3];
            }
            Bt[e2 * 32 + u2] = 1.0f / ((c0 + c1) + (c2 + c3));
        }
        __syncthreads();

        // ===== row pass: A_i = 1 / sum_j K[i][j] * B[j] =====
        float Breg[8];
        #pragma unroll
        for (int e = 0; e < 8; e++) Breg[e] = Bt[e * 32 + u];   // conflict-free
        float rp[8];
        #pragma unroll
        for (int r = 0; r < 8; r++) {
            uint4 kv = Kh4[(8 * s + r) * U4STR + u];
            float2 f;
            float a;
            f = __half22float2(*(__half2*)&kv.x);
            a = f.x * Breg[0];            a = fmaf(f.y, Breg[1], a);
            f = __half22float2(*(__half2*)&kv.y);
            a = fmaf(f.x, Breg[2], a);    a = fmaf(f.y, Breg[3], a);
            f = __half22float2(*(__half2*)&kv.z);
            a = fmaf(f.x, Breg[4], a);    a = fmaf(f.y, Breg[5], a);
            f = __half22float2(*(__half2*)&kv.w);
            a = fmaf(f.x, Breg[6], a);    a = fmaf(f.y, Breg[7], a);
            rp[r] = a;
        }
        // stage partials: red[i*33 + u], lanes vary u -> conflict-free
        #pragma unroll
        for (int r = 0; r < 8; r++) red[(8 * s + r) * 33 + u] = rp[r];
        __syncthreads();
        if (t < NN) {   // row i = t ; reduce over 32 column-groups
            const float* p = red + t * 33;
            float c0 = 0, c1 = 0, c2 = 0, c3 = 0;
            #pragma unroll
            for (int k = 0; k < 32; k += 4) {
                c0 += p[k]; c1 += p[k + 1]; c2 += p[k + 2]; c3 += p[k + 3];
            }
            A[t] = 1.0f / ((c0 + c1) + (c2 + c3));
        }
        __syncthreads();
    }

    // ---------------- epilogue: out = exp(x) * A_i * B_j (fp32 exp!) ----------------
    if (t < NN) red[t] = Bt[(t & 7) * 32 + (t >> 3)];   // natural-order B
    __syncthreads();
    const float* Bn = red;
    #pragma unroll 4
    for (int k = 0; k < 16; k++) {
        int idx = (k * THREADS + t) * 4;
        float4 v = *(const float4*)(xm + idx);
        int i = idx >> 8, j = idx & 255;
        float ai = A[i];                         // warp-uniform broadcast
        float4 bv = *(const float4*)(Bn + j);
        float4 o;
        o.x = __expf(v.x) * ai * bv.x;
        o.y = __expf(v.y) * ai * bv.y;
        o.z = __expf(v.z) * ai * bv.z;
        o.w = __expf(v.w) * ai * bv.w;
        *(float4*)(om + idx) = o;
    }
}

extern "C" void kernel_launch(void* const* d_in, const int* in_sizes, int n_in,
                              void* d_out, int out_size) {
    const float* x = (const float*)d_in[0];
    float* out = (float*)d_out;
    int n_mat = in_sizes[0] / (NN * NN);        // 512
    cudaFuncSetAttribute(sinkhorn_kernel,
                         cudaFuncAttributeMaxDynamicSharedMemorySize, SM_BYTES);
    sinkhorn_kernel<<<n_mat, THREADS, SM_BYTES>>>(x, out);
}

// round 4
// speedup vs baseline: 2.9417x; 1.5775x over previous
#include <cuda_runtime.h>
#include <cuda_fp16.h>

#define NN 256
#define THREADS 512
#define ITERS 20

// smem union layout (bytes):
//   [0, 33792)      setup chunk Ksm (64 rows x 264 halves)  OR  redr (8448 floats)
//   [33792, 50688)  redc (4224 half2)
//   [50688, 51712)  Ah2 (256 half2)
//   [51712, 52224)  Bth2 (128 half2)
//   [52224, 53248)  Bf (256 float)
//   [53248, 54272)  Af (256 float)
#define SM_BYTES 54272

__global__ __launch_bounds__(THREADS, 1)
void sinkhorn_kernel(const float* __restrict__ x, float* __restrict__ out) {
    extern __shared__ char sm[];
    float*   redr = (float*)sm;
    __half2* redc = (__half2*)(sm + 33792);
    __half2* Ah2  = (__half2*)(sm + 50688);
    __half2* Bth2 = (__half2*)(sm + 51712);
    float*   Bf   = (float*)(sm + 52224);
    float*   Af   = (float*)(sm + 53248);
    __half*  Ksm  = (__half*)sm;          // setup staging (overlaps redr)
    uint4*   Ksm4 = (uint4*)sm;

    const int t = threadIdx.x;
    const int u = t & 31;          // uint4-column: halves 8u..8u+7 (half2 cols 4u..4u+3)
    const int s = t >> 5;          // row slice: rows 16s..16s+15
    const size_t base = (size_t)blockIdx.x * (NN * NN);
    const float* xm = x + base;
    float* om = out + base;

    uint4 kv[16];                  // register-resident K tile (fp16), whole kernel

    // ---------------- setup: 4 chunks of 64 rows through smem ----------------
    #pragma unroll
    for (int q = 0; q < 4; q++) {
        #pragma unroll
        for (int k = 0; k < 8; k++) {
            int idx = (k * THREADS + t) * 4;
            float4 v = *(const float4*)(xm + q * 64 * NN + idx);
            int ic = idx >> 8, j = idx & 255;
            *(__half2*)(Ksm + ic * 264 + j)     = __floats2half2_rn(__expf(v.x), __expf(v.y));
            *(__half2*)(Ksm + ic * 264 + j + 2) = __floats2half2_rn(__expf(v.z), __expf(v.w));
        }
        __syncthreads();
        if ((s >> 2) == q) {               // this thread's 16 rows live in this chunk
            #pragma unroll
            for (int r = 0; r < 16; r++)
                kv[r] = Ksm4[(16 * (s & 3) + r) * 33 + u];   // conflict-free
        }
        __syncthreads();
    }
    if (t < NN) Ah2[t] = __floats2half2_rn(1.0f, 1.0f);
    __syncthreads();

    // ---------------- main loop ----------------
    for (int it = 0; it < ITERS; it++) {
        // ===== column pass: partial col sums via HFMA2 (16-term half2 chains) =====
        __half2 z = __floats2half2_rn(0.f, 0.f);
        __half2 acc0 = z, acc1 = z, acc2 = z, acc3 = z;
        #pragma unroll
        for (int r = 0; r < 16; r++) {
            __half2 a2 = Ah2[16 * s + r];                    // warp-uniform broadcast
            const __half2* kh = (const __half2*)&kv[r];
            acc0 = __hfma2(kh[0], a2, acc0);
            acc1 = __hfma2(kh[1], a2, acc1);
            acc2 = __hfma2(kh[2], a2, acc2);
            acc3 = __hfma2(kh[3], a2, acc3);
        }
        redc[0 * 1056 + u * 33 + s] = acc0;   // bank = (u+s)%32, conflict-free
        redc[1 * 1056 + u * 33 + s] = acc1;
        redc[2 * 1056 + u * 33 + s] = acc2;
        redc[3 * 1056 + u * 33 + s] = acc3;
        __syncthreads();
        if (t < 128) {                         // fp32 cross-slice reduce + rcp
            int q = t >> 5, u2 = t & 31;
            const __half2* p = redc + q * 1056 + u2 * 33;    // stride 33, conflict-free
            float c0 = 0.f, c1 = 0.f;
            #pragma unroll
            for (int k = 0; k < 16; k++) {
                float2 f = __half22float2(p[k]);
                c0 += f.x; c1 += f.y;
            }
            float b0 = 1.0f / c0, b1 = 1.0f / c1;
            int j2 = 4 * u2 + q;
            Bth2[j2] = __floats2half2_rn(b0, b1);
            Bf[2 * j2]     = b0;
            Bf[2 * j2 + 1] = b1;
        }
        __syncthreads();

        // ===== row pass: per-row 8-col partials (4-term half2 chains -> fp32) =====
        uint4 bt = *(const uint4*)(Bth2 + 4 * u);            // LDS.128, conflict-free
        const __half2* b2 = (const __half2*)&bt;
        #pragma unroll
        for (int r = 0; r < 16; r++) {
            const __half2* kh = (const __half2*)&kv[r];
            __half2 pr = __hmul2(kh[0], b2[0]);
            pr = __hfma2(kh[1], b2[1], pr);
            pr = __hfma2(kh[2], b2[2], pr);
            pr = __hfma2(kh[3], b2[3], pr);
            float2 f = __half22float2(pr);
            redr[(16 * s + r) * 33 + u] = f.x + f.y;         // stride 33, conflict-free
        }
        __syncthreads();
        if (t < NN) {                          // fp32 cross-group reduce + rcp
            const float* p = redr + t * 33;
            float c0 = 0, c1 = 0, c2 = 0, c3 = 0;
            #pragma unroll
            for (int k = 0; k < 32; k += 4) {
                c0 += p[k]; c1 += p[k + 1]; c2 += p[k + 2]; c3 += p[k + 3];
            }
            float a = 1.0f / ((c0 + c1) + (c2 + c3));
            Ah2[t] = __floats2half2_rn(a, a);
            Af[t] = a;
        }
        __syncthreads();
    }

    // ---------------- epilogue: out = exp(x) * A_i * B_j (fp32 exp) ----------------
    #pragma unroll 4
    for (int k = 0; k < 32; k++) {
        int idx = (k * THREADS + t) * 4;
        float4 v = *(const float4*)(xm + idx);
        int i = idx >> 8, j = idx & 255;
        float ai = Af[i];
        float4 bv = *(const float4*)(Bf + j);
        float4 o;
        o.x = __expf(v.x) * ai * bv.x;
        o.y = __expf(v.y) * ai * bv.y;
        o.z = __expf(v.z) * ai * bv.z;
        o.w = __expf(v.w) * ai * bv.w;
        *(float4*)(om + idx) = o;
    }
}

extern "C" void kernel_launch(void* const* d_in, const int* in_sizes, int n_in,
                              void* d_out, int out_size) {
    const float* x = (const float*)d_in[0];
    float* out = (float*)d_out;
    int n_mat = in_sizes[0] / (NN * NN);      // 512
    cudaFuncSetAttribute(sinkhorn_kernel,
                         cudaFuncAttributeMaxDynamicSharedMemorySize, SM_BYTES);
    sinkhorn_kernel<<<n_mat, THREADS, SM_BYTES>>>(x, out);
}